// round 11
// baseline (speedup 1.0000x reference)
#include <cuda_runtime.h>
#include <math.h>

#define Bn 1024
#define Sn 100
#define En 128
#define Hn 128
#define GPB 8                 // batches per block
#define NBLK (Bn / GPB)       // 128 persistent blocks

// ---------------- scratch (device globals; no allocations allowed) ----------
__device__ float d_eg[(size_t)Bn * Sn * Hn];   // raw e_g  [b][s][h]
__device__ float d_tg[(size_t)Bn * Sn * Hn];   // tanh(e_g)
__device__ float d_tp[(size_t)Bn * Sn * Hn];   // tanh(e_p)

#define NEGINF __int_as_float(0xff800000)

__device__ __forceinline__ float sigf(float x) { return 1.0f / (1.0f + expf(-x)); }

__device__ __forceinline__ float warp_sum(float v) {
#pragma unroll
    for (int o = 16; o > 0; o >>= 1) v += __shfl_xor_sync(0xffffffffu, v, o);
    return v;
}
__device__ __forceinline__ float warp_max(float v) {
#pragma unroll
    for (int o = 16; o > 0; o >>= 1) v = fmaxf(v, __shfl_xor_sync(0xffffffffu, v, o));
    return v;
}
__device__ __forceinline__ int warp_min_i(int v) {
#pragma unroll
    for (int o = 16; o > 0; o >>= 1) v = min(v, __shfl_xor_sync(0xffffffffu, v, o));
    return v;
}

// ---------------- precompute e_g, tanh(e_g), tanh(e_p) ----------------------
__global__ void k_pre(const float* __restrict__ ctx,
                      const float* __restrict__ Wg, const float* __restrict__ bg,
                      const float* __restrict__ Wp, const float* __restrict__ bp) {
    extern __shared__ float sm[];
    float* Wsm = sm;             // [k][o] pitch 129
    float* Csm = sm + 128 * 129; // [k][b] pitch 128
    int b0 = blockIdx.x * 128;
    int s  = blockIdx.y;
    int z  = blockIdx.z;
    const float* W    = z ? Wp : Wg;
    const float* bias = z ? bp : bg;
    int tid = threadIdx.x;

    for (int idx = tid; idx < 128 * 128; idx += 256) {
        int o = idx >> 7, k = idx & 127;
        Wsm[k * 129 + o] = W[idx];
    }
    const float* cbase = ctx + (size_t)s * Hn * Bn + b0;
    for (int idx = tid; idx < 128 * 128; idx += 256) {
        int h = idx >> 7, bb = idx & 127;
        Csm[h * 128 + bb] = cbase[(size_t)h * Bn + bb];
    }
    __syncthreads();

    int tx = tid & 31, ty = tid >> 5;
    float acc[4][16];
#pragma unroll
    for (int i = 0; i < 4; i++)
#pragma unroll
        for (int j = 0; j < 16; j++) acc[i][j] = 0.0f;

    for (int k = 0; k < 128; k++) {
        float wv[4];
#pragma unroll
        for (int i = 0; i < 4; i++) wv[i] = Wsm[k * 129 + tx + 32 * i];
#pragma unroll
        for (int j = 0; j < 16; j++) {
            float cv = Csm[k * 128 + ty * 16 + j];
#pragma unroll
            for (int i = 0; i < 4; i++) acc[i][j] = fmaf(wv[i], cv, acc[i][j]);
        }
    }

#pragma unroll
    for (int j = 0; j < 16; j++) {
        int b = b0 + ty * 16 + j;
#pragma unroll
        for (int i = 0; i < 4; i++) {
            int o = tx + 32 * i;
            float val = acc[i][j] + bias[o];
            size_t off = ((size_t)b * Sn + s) * Hn + o;
            float tv = tanhf(val);
            if (z == 0) { d_eg[off] = val; d_tg[off] = tv; }
            else        { d_tp[off] = tv; }
        }
    }
}

// ---------------- persistent per-batch-group decoder loop --------------------
__global__ void __launch_bounds__(256, 1)
k_loop(const float* __restrict__ dec, const float* __restrict__ emb,
       const float* __restrict__ h0,  const float* __restrict__ c0,
       const float* __restrict__ Wi,  const float* __restrict__ bi,
       const float* __restrict__ Wh,  const float* __restrict__ bh,
       const float* __restrict__ gWq, const float* __restrict__ gbq,
       const float* __restrict__ gv,
       const float* __restrict__ pWq, const float* __restrict__ pbq,
       const float* __restrict__ pv,
       float* __restrict__ out) {
    __shared__ __align__(16) float sh_h [GPB * Hn];
    __shared__ __align__(16) float sh_c [GPB * Hn];
    __shared__ __align__(16) float sh_x [GPB * En];
    __shared__ __align__(16) float sh_tq[GPB * Hn];
    __shared__ __align__(16) float sh_gl[GPB * Hn];
    __shared__ __align__(16) float sh_u [GPB * Sn];
    __shared__ __align__(16) float sh_w [GPB * Sn];
    __shared__ __align__(16) float scr  [32 * 128];      // gates partials [c][ul]
    __shared__ __align__(16) float sh_bias[4 * Hn];      // bi + bh
    __shared__ __align__(16) float sh_gv[Hn];
    __shared__ __align__(16) float sh_pv[Hn];
    __shared__ unsigned char sh_mask[GPB * Sn];
    __shared__ int sh_sidx[GPB];

    const int tid = threadIdx.x;
    const int b0  = blockIdx.x * GPB;

    // prologue: resident state
    for (int i = tid; i < GPB * Hn; i += 256) {
        sh_h[i] = h0[b0 * Hn + i];
        sh_c[i] = c0[b0 * Hn + i];
        sh_x[i] = dec[b0 * En + i];
    }
    for (int i = tid; i < 4 * Hn; i += 256) sh_bias[i] = bi[i] + bh[i];
    for (int i = tid; i < Hn; i += 256) { sh_gv[i] = gv[i]; sh_pv[i] = pv[i]; }
    for (int i = tid; i < GPB * Sn; i += 256) sh_mask[i] = 0;
    __syncthreads();

    const int ul = tid & 127;     // unit lane (gates / gemm output lane)
    const int kg = tid >> 7;      // k-half group for gates
    const int wp = tid >> 5;      // warp id = batch id for attention
    const int ln = tid & 31;

    for (int t = 0; t < Sn; t++) {
        // ===== Stage 1: LSTM gates GEMM (split-k over {x·Wi, h·Wh}) =====
        {
            const float* W = kg ? Wh : Wi;
            const float* A = kg ? sh_h : sh_x;
            float acc[4][GPB];
#pragma unroll
            for (int g = 0; g < 4; g++)
#pragma unroll
                for (int b = 0; b < GPB; b++) acc[g][b] = 0.0f;

            const float* w0 = W + (0 * 128 + ul) * 128;
            const float* w1 = W + (1 * 128 + ul) * 128;
            const float* w2 = W + (2 * 128 + ul) * 128;
            const float* w3 = W + (3 * 128 + ul) * 128;
#pragma unroll 2
            for (int k = 0; k < 128; k += 4) {
                float4 wv0 = *(const float4*)(w0 + k);
                float4 wv1 = *(const float4*)(w1 + k);
                float4 wv2 = *(const float4*)(w2 + k);
                float4 wv3 = *(const float4*)(w3 + k);
#pragma unroll
                for (int b = 0; b < GPB; b++) {
                    float4 av = *(const float4*)(A + b * 128 + k);
                    acc[0][b] = fmaf(wv0.x, av.x, acc[0][b]);
                    acc[0][b] = fmaf(wv0.y, av.y, acc[0][b]);
                    acc[0][b] = fmaf(wv0.z, av.z, acc[0][b]);
                    acc[0][b] = fmaf(wv0.w, av.w, acc[0][b]);
                    acc[1][b] = fmaf(wv1.x, av.x, acc[1][b]);
                    acc[1][b] = fmaf(wv1.y, av.y, acc[1][b]);
                    acc[1][b] = fmaf(wv1.z, av.z, acc[1][b]);
                    acc[1][b] = fmaf(wv1.w, av.w, acc[1][b]);
                    acc[2][b] = fmaf(wv2.x, av.x, acc[2][b]);
                    acc[2][b] = fmaf(wv2.y, av.y, acc[2][b]);
                    acc[2][b] = fmaf(wv2.z, av.z, acc[2][b]);
                    acc[2][b] = fmaf(wv2.w, av.w, acc[2][b]);
                    acc[3][b] = fmaf(wv3.x, av.x, acc[3][b]);
                    acc[3][b] = fmaf(wv3.y, av.y, acc[3][b]);
                    acc[3][b] = fmaf(wv3.z, av.z, acc[3][b]);
                    acc[3][b] = fmaf(wv3.w, av.w, acc[3][b]);
                }
            }
            if (kg) {
#pragma unroll
                for (int g = 0; g < 4; g++)
#pragma unroll
                    for (int b = 0; b < GPB; b++)
                        scr[(g * GPB + b) * 128 + ul] = acc[g][b];
            }
            __syncthreads();
            if (!kg) {
#pragma unroll
                for (int b = 0; b < GPB; b++) {
                    float iv = acc[0][b] + scr[(0 * GPB + b) * 128 + ul] + sh_bias[0 * 128 + ul];
                    float fv = acc[1][b] + scr[(1 * GPB + b) * 128 + ul] + sh_bias[1 * 128 + ul];
                    float gg = acc[2][b] + scr[(2 * GPB + b) * 128 + ul] + sh_bias[2 * 128 + ul];
                    float ov = acc[3][b] + scr[(3 * GPB + b) * 128 + ul] + sh_bias[3 * 128 + ul];
                    float c  = sh_c[b * 128 + ul];
                    float cy = sigf(fv) * c + sigf(iv) * tanhf(gg);
                    float hy = sigf(ov) * tanhf(cy);
                    sh_c[b * 128 + ul] = cy;
                    sh_h[b * 128 + ul] = hy;
                }
            }
            __syncthreads();
        }

        // ===== Stage 2: q = tanh(h @ gWq^T + gbq) =====
        {
            const int bg = kg;                   // 2 batch groups of 4
            float a4[4] = {0.f, 0.f, 0.f, 0.f};
            const float* wrow = gWq + ul * 128;
#pragma unroll 2
            for (int k = 0; k < 128; k += 4) {
                float4 wv = *(const float4*)(wrow + k);
#pragma unroll
                for (int bb = 0; bb < 4; bb++) {
                    float4 hv = *(const float4*)(sh_h + (bg * 4 + bb) * 128 + k);
                    a4[bb] = fmaf(wv.x, hv.x, a4[bb]);
                    a4[bb] = fmaf(wv.y, hv.y, a4[bb]);
                    a4[bb] = fmaf(wv.z, hv.z, a4[bb]);
                    a4[bb] = fmaf(wv.w, hv.w, a4[bb]);
                }
            }
            float bq = gbq[ul];
#pragma unroll
            for (int bb = 0; bb < 4; bb++)
                sh_tq[(bg * 4 + bb) * 128 + ul] = tanhf(a4[bb] + bq);
            __syncthreads();
        }

        // ===== Stage 3: glimpse attention + softmax (one warp per batch) =====
        {
            const int b = wp;
            float4 tq = *(const float4*)(sh_tq + b * 128 + 4 * ln);
            float4 vv = *(const float4*)(sh_gv + 4 * ln);
            const float* tgb = d_tg + (size_t)(b0 + b) * Sn * Hn + 4 * ln;
#pragma unroll 2
            for (int s = 0; s < Sn; s++) {
                float u;
                if (sh_mask[b * Sn + s]) {
                    u = NEGINF;
                } else {
                    float4 te = *(const float4*)(tgb + s * Hn);
                    float a;
                    a = vv.x * __fdividef(tq.x + te.x, fmaf(tq.x, te.x, 1.0f));
                    a = fmaf(vv.y, __fdividef(tq.y + te.y, fmaf(tq.y, te.y, 1.0f)), a);
                    a = fmaf(vv.z, __fdividef(tq.z + te.z, fmaf(tq.z, te.z, 1.0f)), a);
                    a = fmaf(vv.w, __fdividef(tq.w + te.w, fmaf(tq.w, te.w, 1.0f)), a);
                    u = warp_sum(a);
                }
                if (ln == 0) sh_u[b * Sn + s] = u;
            }
            __syncwarp();
            // softmax over s for batch b
            float v0[4];
#pragma unroll
            for (int k = 0; k < 4; k++) {
                int s = ln + 32 * k;
                v0[k] = (s < Sn) ? sh_u[b * Sn + s] : NEGINF;
            }
            float m = warp_max(fmaxf(fmaxf(v0[0], v0[1]), fmaxf(v0[2], v0[3])));
            float e[4], loc = 0.0f;
#pragma unroll
            for (int k = 0; k < 4; k++) {
                int s = ln + 32 * k;
                e[k] = (s < Sn) ? expf(v0[k] - m) : 0.0f;
                loc += e[k];
            }
            float inv = 1.0f / warp_sum(loc);
#pragma unroll
            for (int k = 0; k < 4; k++) {
                int s = ln + 32 * k;
                if (s < Sn) sh_w[b * Sn + s] = e[k] * inv;
            }
            __syncthreads();
        }

        // ===== Stage 4a: gl = sum_s w[s] * e_g[b,s,:] (skip w==0) =====
        {
            const int b = wp;
            const float* egb = d_eg + (size_t)(b0 + b) * Sn * Hn + 4 * ln;
            float4 acc = make_float4(0.f, 0.f, 0.f, 0.f);
#pragma unroll 2
            for (int s = 0; s < Sn; s++) {
                float ws = sh_w[b * Sn + s];
                if (ws != 0.0f) {
                    float4 ev = *(const float4*)(egb + (size_t)s * Hn);
                    acc.x = fmaf(ws, ev.x, acc.x);
                    acc.y = fmaf(ws, ev.y, acc.y);
                    acc.z = fmaf(ws, ev.z, acc.z);
                    acc.w = fmaf(ws, ev.w, acc.w);
                }
            }
            *(float4*)(sh_gl + b * 128 + 4 * ln) = acc;
            __syncthreads();
        }

        // ===== Stage 4b: qp = tanh(gl @ pWq^T + pbq) =====
        {
            const int bg = kg;
            float a4[4] = {0.f, 0.f, 0.f, 0.f};
            const float* wrow = pWq + ul * 128;
#pragma unroll 2
            for (int k = 0; k < 128; k += 4) {
                float4 wv = *(const float4*)(wrow + k);
#pragma unroll
                for (int bb = 0; bb < 4; bb++) {
                    float4 gvv = *(const float4*)(sh_gl + (bg * 4 + bb) * 128 + k);
                    a4[bb] = fmaf(wv.x, gvv.x, a4[bb]);
                    a4[bb] = fmaf(wv.y, gvv.y, a4[bb]);
                    a4[bb] = fmaf(wv.z, gvv.z, a4[bb]);
                    a4[bb] = fmaf(wv.w, gvv.w, a4[bb]);
                }
            }
            float bq = pbq[ul];
#pragma unroll
            for (int bb = 0; bb < 4; bb++)
                sh_tq[(bg * 4 + bb) * 128 + ul] = tanhf(a4[bb] + bq);
            __syncthreads();
        }

        // ===== Stage 5: pointer attention, softmax, probs, argmax, gather ====
        {
            const int b = wp;
            float4 tq = *(const float4*)(sh_tq + b * 128 + 4 * ln);
            float4 vv = *(const float4*)(sh_pv + 4 * ln);
            const float* tpb = d_tp + (size_t)(b0 + b) * Sn * Hn + 4 * ln;
#pragma unroll 2
            for (int s = 0; s < Sn; s++) {
                float u;
                if (sh_mask[b * Sn + s]) {
                    u = NEGINF;
                } else {
                    float4 te = *(const float4*)(tpb + s * Hn);
                    float a;
                    a = vv.x * __fdividef(tq.x + te.x, fmaf(tq.x, te.x, 1.0f));
                    a = fmaf(vv.y, __fdividef(tq.y + te.y, fmaf(tq.y, te.y, 1.0f)), a);
                    a = fmaf(vv.z, __fdividef(tq.z + te.z, fmaf(tq.z, te.z, 1.0f)), a);
                    a = fmaf(vv.w, __fdividef(tq.w + te.w, fmaf(tq.w, te.w, 1.0f)), a);
                    a = warp_sum(a);
                    u = 10.0f * tanhf(a);
                }
                if (ln == 0) sh_u[b * Sn + s] = u;
            }
            __syncwarp();
            float v0[4];
#pragma unroll
            for (int k = 0; k < 4; k++) {
                int s = ln + 32 * k;
                v0[k] = (s < Sn) ? sh_u[b * Sn + s] : NEGINF;
            }
            float m = warp_max(fmaxf(fmaxf(v0[0], v0[1]), fmaxf(v0[2], v0[3])));
            float e[4], loc = 0.0f;
#pragma unroll
            for (int k = 0; k < 4; k++) {
                int s = ln + 32 * k;
                e[k] = (s < Sn) ? expf(v0[k] - m) : 0.0f;
                loc += e[k];
            }
            float inv = 1.0f / warp_sum(loc);
            size_t pb = ((size_t)t * Bn + (b0 + b)) * Sn;
#pragma unroll
            for (int k = 0; k < 4; k++) {
                int s = ln + 32 * k;
                if (s < Sn) out[pb + s] = e[k] * inv;
            }
            // argmax (first index wins ties): smallest s with v0 == m
            int cand = 1 << 30;
#pragma unroll
            for (int k = 0; k < 4; k++) {
                int s = ln + 32 * k;
                if (s < Sn && v0[k] == m) cand = min(cand, s);
            }
            cand = warp_min_i(cand);
            if (ln == 0) {
                out[(size_t)Sn * Bn * Sn + (size_t)t * Bn + (b0 + b)] = (float)cand;
                sh_mask[b * Sn + cand] = 1;
                sh_sidx[b] = cand;
            }
            __syncthreads();
            // gather next decoder input: x[b,:] = emb[idx, b, :]
            for (int i = tid; i < GPB * En; i += 256) {
                int bb = i >> 7, ee = i & 127;
                sh_x[i] = emb[((size_t)sh_sidx[bb] * Bn + (b0 + bb)) * En + ee];
            }
            __syncthreads();
        }
    }

    // epilogue: write final hx, cx
    size_t base = (size_t)Sn * Bn * Sn + (size_t)Sn * Bn;
    for (int i = tid; i < GPB * Hn; i += 256) {
        out[base + b0 * Hn + i] = sh_h[i];
        out[base + (size_t)Bn * Hn + b0 * Hn + i] = sh_c[i];
    }
}

// ---------------- host launch ------------------------------------------------
extern "C" void kernel_launch(void* const* d_in, const int* in_sizes, int n_in,
                              void* d_out, int out_size) {
    const float* dec = (const float*)d_in[0];
    const float* emb = (const float*)d_in[1];
    const float* h0  = (const float*)d_in[2];
    const float* c0  = (const float*)d_in[3];
    const float* ctx = (const float*)d_in[4];
    const float* Wi  = (const float*)d_in[5];
    const float* bi  = (const float*)d_in[6];
    const float* Wh  = (const float*)d_in[7];
    const float* bh  = (const float*)d_in[8];
    const float* gWq = (const float*)d_in[9];
    const float* gbq = (const float*)d_in[10];
    const float* gWr = (const float*)d_in[11];
    const float* gbr = (const float*)d_in[12];
    const float* gv  = (const float*)d_in[13];
    const float* pWq = (const float*)d_in[14];
    const float* pbq = (const float*)d_in[15];
    const float* pWr = (const float*)d_in[16];
    const float* pbr = (const float*)d_in[17];
    const float* pv  = (const float*)d_in[18];
    float* out = (float*)d_out;

    const int SM_PRE = (128 * 129 + 128 * 128) * 4;  // 131584
    cudaFuncSetAttribute(k_pre, cudaFuncAttributeMaxDynamicSharedMemorySize, SM_PRE);

    k_pre<<<dim3(Bn / 128, Sn, 2), 256, SM_PRE>>>(ctx, gWr, gbr, pWr, pbr);
    k_loop<<<NBLK, 256>>>(dec, emb, h0, c0, Wi, bi, Wh, bh,
                          gWq, gbq, gv, pWq, pbq, pv, out);
}

// round 12
// speedup vs baseline: 1.8878x; 1.8878x over previous
#include <cuda_runtime.h>
#include <math.h>

#define Bn 1024
#define Sn 100
#define En 128
#define Hn 128
#define GPB 8                 // batches per block
#define NBLK (Bn / GPB)       // 128 persistent blocks
#define NT 512                // threads per block

// ---------------- scratch (device globals; no allocations allowed) ----------
__device__ float d_eg[(size_t)Bn * Sn * Hn];   // raw e_g  [b][s][h]
__device__ float d_tg[(size_t)Bn * Sn * Hn];   // tanh(e_g)
__device__ float d_tp[(size_t)Bn * Sn * Hn];   // tanh(e_p)
__device__ float d_WiT[128 * 128 * 4];         // [k][unit][gate]
__device__ float d_WhT[128 * 128 * 4];         // [k][unit][gate]
__device__ float d_gWqT[128 * 128];            // [k][o]
__device__ float d_pWqT[128 * 128];            // [k][o]

#define NEGINF __int_as_float(0xff800000)

__device__ __forceinline__ float sigf(float x) { return 1.0f / (1.0f + expf(-x)); }

__device__ __forceinline__ float warp_sum(float v) {
#pragma unroll
    for (int o = 16; o > 0; o >>= 1) v += __shfl_xor_sync(0xffffffffu, v, o);
    return v;
}
__device__ __forceinline__ float warp_max(float v) {
#pragma unroll
    for (int o = 16; o > 0; o >>= 1) v = fmaxf(v, __shfl_xor_sync(0xffffffffu, v, o));
    return v;
}
__device__ __forceinline__ int warp_min_i(int v) {
#pragma unroll
    for (int o = 16; o > 0; o >>= 1) v = min(v, __shfl_xor_sync(0xffffffffu, v, o));
    return v;
}

// ---------------- weight transposes (one-time) -------------------------------
__global__ void k_tw(const float* __restrict__ Wi, const float* __restrict__ Wh,
                     const float* __restrict__ gWq, const float* __restrict__ pWq) {
    int i = blockIdx.x * 256 + threadIdx.x;
    if (i < 65536) {
        int r = i >> 7;          // source row 0..511
        int k = i & 127;
        int g = r >> 7, ul = r & 127;
        d_WiT[(k * 128 + ul) * 4 + g] = Wi[i];
        d_WhT[(k * 128 + ul) * 4 + g] = Wh[i];
    }
    if (i < 16384) {
        int o = i >> 7, k = i & 127;
        d_gWqT[k * 128 + o] = gWq[i];
        d_pWqT[k * 128 + o] = pWq[i];
    }
}

// ---------------- precompute e_g, tanh(e_g), tanh(e_p) ----------------------
__global__ void k_pre(const float* __restrict__ ctx,
                      const float* __restrict__ Wg, const float* __restrict__ bg,
                      const float* __restrict__ Wp, const float* __restrict__ bp) {
    extern __shared__ float sm[];
    float* Wsm = sm;             // [k][o] pitch 129
    float* Csm = sm + 128 * 129; // [k][b] pitch 128
    int b0 = blockIdx.x * 128;
    int s  = blockIdx.y;
    int z  = blockIdx.z;
    const float* W    = z ? Wp : Wg;
    const float* bias = z ? bp : bg;
    int tid = threadIdx.x;

    for (int idx = tid; idx < 128 * 128; idx += 256) {
        int o = idx >> 7, k = idx & 127;
        Wsm[k * 129 + o] = W[idx];
    }
    const float* cbase = ctx + (size_t)s * Hn * Bn + b0;
    for (int idx = tid; idx < 128 * 128; idx += 256) {
        int h = idx >> 7, bb = idx & 127;
        Csm[h * 128 + bb] = cbase[(size_t)h * Bn + bb];
    }
    __syncthreads();

    int tx = tid & 31, ty = tid >> 5;
    float acc[4][16];
#pragma unroll
    for (int i = 0; i < 4; i++)
#pragma unroll
        for (int j = 0; j < 16; j++) acc[i][j] = 0.0f;

    for (int k = 0; k < 128; k++) {
        float wv[4];
#pragma unroll
        for (int i = 0; i < 4; i++) wv[i] = Wsm[k * 129 + tx + 32 * i];
#pragma unroll
        for (int j = 0; j < 16; j++) {
            float cv = Csm[k * 128 + ty * 16 + j];
#pragma unroll
            for (int i = 0; i < 4; i++) acc[i][j] = fmaf(wv[i], cv, acc[i][j]);
        }
    }

#pragma unroll
    for (int j = 0; j < 16; j++) {
        int b = b0 + ty * 16 + j;
#pragma unroll
        for (int i = 0; i < 4; i++) {
            int o = tx + 32 * i;
            float val = acc[i][j] + bias[o];
            size_t off = ((size_t)b * Sn + s) * Hn + o;
            float tv = tanhf(val);
            if (z == 0) { d_eg[off] = val; d_tg[off] = tv; }
            else        { d_tp[off] = tv; }
        }
    }
}

// ---------------- persistent decoder loop ------------------------------------
struct Smem {
    float h[GPB * Hn];
    float c[GPB * Hn];
    float x[GPB * En];
    float tq[GPB * Hn];
    float glA[GPB * Hn];
    float glB[GPB * Hn];
    float u[GPB * Sn];
    float w[GPB * Sn];
    float scr[4 * 4 * GPB * Hn];   // [kg][gate][b][ul]
    float bias[4 * Hn];
    float gv[Hn];
    float pv[Hn];
    int   list[GPB * Sn];
    int   cnt[GPB];
    int   sidx[GPB];
    unsigned char mask[GPB * Sn];
};

__global__ void __launch_bounds__(NT, 1)
k_loop(const float* __restrict__ dec, const float* __restrict__ emb,
       const float* __restrict__ h0,  const float* __restrict__ c0,
       const float* __restrict__ bi,  const float* __restrict__ bh,
       const float* __restrict__ gbq, const float* __restrict__ gv,
       const float* __restrict__ pbq, const float* __restrict__ pv,
       float* __restrict__ out) {
    extern __shared__ unsigned char sm_raw[];
    Smem& S = *reinterpret_cast<Smem*>(sm_raw);

    const int tid = threadIdx.x;
    const int b0  = blockIdx.x * GPB;

    // prologue
    for (int i = tid; i < GPB * Hn; i += NT) {
        S.h[i] = h0[b0 * Hn + i];
        S.c[i] = c0[b0 * Hn + i];
        S.x[i] = dec[b0 * En + i];
    }
    for (int i = tid; i < 4 * Hn; i += NT) S.bias[i] = bi[i] + bh[i];
    for (int i = tid; i < Hn; i += NT) { S.gv[i] = gv[i]; S.pv[i] = pv[i]; }
    for (int i = tid; i < GPB * Sn; i += NT) S.mask[i] = 0;
    __syncthreads();

    const int ul  = tid & 127;       // output lane for GEMMs
    const int kg  = tid >> 7;        // group 0..3
    const int wid = tid >> 5;        // warp 0..15
    const int ln  = tid & 31;
    const int ab  = wid >> 1;        // attention batch 0..7
    const int wh  = wid & 1;         // attention half-warp pair index
    const int half = ln >> 4;        // half within warp
    const int q16  = ln & 15;

    for (int t = 0; t < Sn; t++) {
        // ===== Stage 0: compact list of unmasked s (warps 0-7) =====
        if (wid < 8) {
            int b = wid;
            int base = 0;
#pragma unroll
            for (int cch = 0; cch < 4; cch++) {
                int s = cch * 32 + ln;
                bool ok = (s < Sn) && (S.mask[b * Sn + s] == 0);
                unsigned bal = __ballot_sync(0xffffffffu, ok);
                if (ok) S.list[b * Sn + base + __popc(bal & ((1u << ln) - 1u))] = s;
                base += __popc(bal);
            }
            if (ln == 0) S.cnt[b] = base;
        }
        // (no sync needed: list consumed only after later barriers)

        // ===== Stage 1: LSTM gates GEMM, 4-way split-k =====
        {
            const float* WT = (kg < 2) ? d_WiT : d_WhT;
            const float* A  = (kg < 2) ? S.x : S.h;
            const int ko = (kg & 1) * 64;
            float acc[4][GPB];
#pragma unroll
            for (int g = 0; g < 4; g++)
#pragma unroll
                for (int b = 0; b < GPB; b++) acc[g][b] = 0.0f;

#pragma unroll 4
            for (int k = ko; k < ko + 64; k += 4) {
                float4 w0 = *(const float4*)(WT + ((k + 0) * 128 + ul) * 4);
                float4 w1 = *(const float4*)(WT + ((k + 1) * 128 + ul) * 4);
                float4 w2 = *(const float4*)(WT + ((k + 2) * 128 + ul) * 4);
                float4 w3 = *(const float4*)(WT + ((k + 3) * 128 + ul) * 4);
#pragma unroll
                for (int b = 0; b < GPB; b++) {
                    float4 av = *(const float4*)(A + b * 128 + k);
                    acc[0][b] = fmaf(w0.x, av.x, acc[0][b]);
                    acc[0][b] = fmaf(w1.x, av.y, acc[0][b]);
                    acc[0][b] = fmaf(w2.x, av.z, acc[0][b]);
                    acc[0][b] = fmaf(w3.x, av.w, acc[0][b]);
                    acc[1][b] = fmaf(w0.y, av.x, acc[1][b]);
                    acc[1][b] = fmaf(w1.y, av.y, acc[1][b]);
                    acc[1][b] = fmaf(w2.y, av.z, acc[1][b]);
                    acc[1][b] = fmaf(w3.y, av.w, acc[1][b]);
                    acc[2][b] = fmaf(w0.z, av.x, acc[2][b]);
                    acc[2][b] = fmaf(w1.z, av.y, acc[2][b]);
                    acc[2][b] = fmaf(w2.z, av.z, acc[2][b]);
                    acc[2][b] = fmaf(w3.z, av.w, acc[2][b]);
                    acc[3][b] = fmaf(w0.w, av.x, acc[3][b]);
                    acc[3][b] = fmaf(w1.w, av.y, acc[3][b]);
                    acc[3][b] = fmaf(w2.w, av.z, acc[3][b]);
                    acc[3][b] = fmaf(w3.w, av.w, acc[3][b]);
                }
            }
#pragma unroll
            for (int g = 0; g < 4; g++)
#pragma unroll
                for (int b = 0; b < GPB; b++)
                    S.scr[((kg * 4 + g) * GPB + b) * 128 + ul] = acc[g][b];
            __syncthreads();

            // combine + cell update: 1024 cells, 2 per thread
#pragma unroll
            for (int cc = 0; cc < 2; cc++) {
                int cell = tid + cc * NT;
                int b = cell >> 7, u = cell & 127;
                float gs[4];
#pragma unroll
                for (int g = 0; g < 4; g++) {
                    float v = S.bias[g * 128 + u];
#pragma unroll
                    for (int gp = 0; gp < 4; gp++)
                        v += S.scr[((gp * 4 + g) * GPB + b) * 128 + u];
                    gs[g] = v;
                }
                float c  = S.c[b * 128 + u];
                float cy = sigf(gs[1]) * c + sigf(gs[0]) * tanhf(gs[2]);
                float hy = sigf(gs[3]) * tanhf(cy);
                S.c[b * 128 + u] = cy;
                S.h[b * 128 + u] = hy;
            }
            __syncthreads();
        }

        // ===== Stage 2: tq = tanh(h @ gWq^T + gbq), 4 groups x 2 batches =====
        {
            int bb0 = kg * 2;
            float a0 = 0.0f, a1 = 0.0f;
            const float* h0p = S.h + bb0 * 128;
            const float* h1p = S.h + (bb0 + 1) * 128;
#pragma unroll 4
            for (int k = 0; k < 128; k++) {
                float wv = d_gWqT[k * 128 + ul];
                a0 = fmaf(wv, h0p[k], a0);
                a1 = fmaf(wv, h1p[k], a1);
            }
            float bq = gbq[ul];
            S.tq[bb0 * 128 + ul]       = tanhf(a0 + bq);
            S.tq[(bb0 + 1) * 128 + ul] = tanhf(a1 + bq);
            __syncthreads();
        }

        // ===== Stage 3: glimpse attention (2 warps/batch, half-warp per s) ===
        {
            const int b = ab;
            const int m = S.cnt[b];
            const int mh = (m + 1) >> 1;
            const int jbeg = wh * mh;
            const int jend = min(m, jbeg + mh);
            float4 tqa = *(const float4*)(S.tq + b * 128 + q16 * 8);
            float4 tqb = *(const float4*)(S.tq + b * 128 + q16 * 8 + 4);
            float4 vva = *(const float4*)(S.gv + q16 * 8);
            float4 vvb = *(const float4*)(S.gv + q16 * 8 + 4);
            const float* tgb = d_tg + (size_t)(b0 + b) * Sn * Hn + q16 * 8;
            for (int j = jbeg; j < jend; j += 2) {
                int jl = j + half;
                bool valid = jl < jend;
                int s = valid ? S.list[b * Sn + jl] : 0;
                float a = 0.0f;
                if (valid) {
                    const float* row = tgb + (size_t)s * Hn;
                    float4 t1 = *(const float4*)(row);
                    float4 t2 = *(const float4*)(row + 4);
                    a = vva.x * __fdividef(tqa.x + t1.x, fmaf(tqa.x, t1.x, 1.0f));
                    a = fmaf(vva.y, __fdividef(tqa.y + t1.y, fmaf(tqa.y, t1.y, 1.0f)), a);
                    a = fmaf(vva.z, __fdividef(tqa.z + t1.z, fmaf(tqa.z, t1.z, 1.0f)), a);
                    a = fmaf(vva.w, __fdividef(tqa.w + t1.w, fmaf(tqa.w, t1.w, 1.0f)), a);
                    a = fmaf(vvb.x, __fdividef(tqb.x + t2.x, fmaf(tqb.x, t2.x, 1.0f)), a);
                    a = fmaf(vvb.y, __fdividef(tqb.y + t2.y, fmaf(tqb.y, t2.y, 1.0f)), a);
                    a = fmaf(vvb.z, __fdividef(tqb.z + t2.z, fmaf(tqb.z, t2.z, 1.0f)), a);
                    a = fmaf(vvb.w, __fdividef(tqb.w + t2.w, fmaf(tqb.w, t2.w, 1.0f)), a);
                }
#pragma unroll
                for (int o = 8; o > 0; o >>= 1) a += __shfl_xor_sync(0xffffffffu, a, o);
                if (valid && q16 == 0) S.u[b * Sn + s] = a;
            }
            __syncthreads();
        }

        // ===== Stage 3b: glimpse softmax (warps 0-7) =====
        if (wid < 8) {
            int b = wid;
            float v0[4];
#pragma unroll
            for (int k = 0; k < 4; k++) {
                int s = ln + 32 * k;
                v0[k] = (s < Sn && S.mask[b * Sn + s] == 0) ? S.u[b * Sn + s] : NEGINF;
            }
            float mx = warp_max(fmaxf(fmaxf(v0[0], v0[1]), fmaxf(v0[2], v0[3])));
            float e[4], loc = 0.0f;
#pragma unroll
            for (int k = 0; k < 4; k++) {
                int s = ln + 32 * k;
                e[k] = (s < Sn) ? expf(v0[k] - mx) : 0.0f;
                loc += e[k];
            }
            float inv = 1.0f / warp_sum(loc);
#pragma unroll
            for (int k = 0; k < 4; k++) {
                int s = ln + 32 * k;
                if (s < Sn) S.w[b * Sn + s] = e[k] * inv;
            }
        }
        __syncthreads();

        // ===== Stage 4a: gl = sum_s w*e_g over list (2 warps/batch) =====
        {
            const int b = ab;
            const int m = S.cnt[b];
            const int mh = (m + 1) >> 1;
            const int jbeg = wh * mh;
            const int jend = min(m, jbeg + mh);
            const float* egb = d_eg + (size_t)(b0 + b) * Sn * Hn + 4 * ln;
            float4 acc = make_float4(0.f, 0.f, 0.f, 0.f);
            for (int j = jbeg; j < jend; j++) {
                int s = S.list[b * Sn + j];
                float ws = S.w[b * Sn + s];
                float4 ev = *(const float4*)(egb + (size_t)s * Hn);
                acc.x = fmaf(ws, ev.x, acc.x);
                acc.y = fmaf(ws, ev.y, acc.y);
                acc.z = fmaf(ws, ev.z, acc.z);
                acc.w = fmaf(ws, ev.w, acc.w);
            }
            float* dst = (wh ? S.glB : S.glA) + b * 128 + 4 * ln;
            *(float4*)dst = acc;
            __syncthreads();
        }

        // ===== Stage 4b: tq = tanh((glA+glB) @ pWq^T + pbq) =====
        {
            int bb0 = kg * 2;
            float a0 = 0.0f, a1 = 0.0f;
            const float* gA0 = S.glA + bb0 * 128;
            const float* gB0 = S.glB + bb0 * 128;
            const float* gA1 = S.glA + (bb0 + 1) * 128;
            const float* gB1 = S.glB + (bb0 + 1) * 128;
#pragma unroll 4
            for (int k = 0; k < 128; k++) {
                float wv = d_pWqT[k * 128 + ul];
                a0 = fmaf(wv, gA0[k] + gB0[k], a0);
                a1 = fmaf(wv, gA1[k] + gB1[k], a1);
            }
            float bq = pbq[ul];
            S.tq[bb0 * 128 + ul]       = tanhf(a0 + bq);
            S.tq[(bb0 + 1) * 128 + ul] = tanhf(a1 + bq);
            __syncthreads();
        }

        // ===== Stage 5: pointer attention =====
        {
            const int b = ab;
            const int m = S.cnt[b];
            const int mh = (m + 1) >> 1;
            const int jbeg = wh * mh;
            const int jend = min(m, jbeg + mh);
            float4 tqa = *(const float4*)(S.tq + b * 128 + q16 * 8);
            float4 tqb = *(const float4*)(S.tq + b * 128 + q16 * 8 + 4);
            float4 vva = *(const float4*)(S.pv + q16 * 8);
            float4 vvb = *(const float4*)(S.pv + q16 * 8 + 4);
            const float* tpb = d_tp + (size_t)(b0 + b) * Sn * Hn + q16 * 8;
            for (int j = jbeg; j < jend; j += 2) {
                int jl = j + half;
                bool valid = jl < jend;
                int s = valid ? S.list[b * Sn + jl] : 0;
                float a = 0.0f;
                if (valid) {
                    const float* row = tpb + (size_t)s * Hn;
                    float4 t1 = *(const float4*)(row);
                    float4 t2 = *(const float4*)(row + 4);
                    a = vva.x * __fdividef(tqa.x + t1.x, fmaf(tqa.x, t1.x, 1.0f));
                    a = fmaf(vva.y, __fdividef(tqa.y + t1.y, fmaf(tqa.y, t1.y, 1.0f)), a);
                    a = fmaf(vva.z, __fdividef(tqa.z + t1.z, fmaf(tqa.z, t1.z, 1.0f)), a);
                    a = fmaf(vva.w, __fdividef(tqa.w + t1.w, fmaf(tqa.w, t1.w, 1.0f)), a);
                    a = fmaf(vvb.x, __fdividef(tqb.x + t2.x, fmaf(tqb.x, t2.x, 1.0f)), a);
                    a = fmaf(vvb.y, __fdividef(tqb.y + t2.y, fmaf(tqb.y, t2.y, 1.0f)), a);
                    a = fmaf(vvb.z, __fdividef(tqb.z + t2.z, fmaf(tqb.z, t2.z, 1.0f)), a);
                    a = fmaf(vvb.w, __fdividef(tqb.w + t2.w, fmaf(tqb.w, t2.w, 1.0f)), a);
                }
#pragma unroll
                for (int o = 8; o > 0; o >>= 1) a += __shfl_xor_sync(0xffffffffu, a, o);
                if (valid && q16 == 0) S.u[b * Sn + s] = 10.0f * tanhf(a);
            }
            __syncthreads();
        }

        // ===== Stage 5b: pointer softmax + probs + argmax (warps 0-7) =====
        if (wid < 8) {
            int b = wid;
            float v0[4];
#pragma unroll
            for (int k = 0; k < 4; k++) {
                int s = ln + 32 * k;
                v0[k] = (s < Sn && S.mask[b * Sn + s] == 0) ? S.u[b * Sn + s] : NEGINF;
            }
            float mx = warp_max(fmaxf(fmaxf(v0[0], v0[1]), fmaxf(v0[2], v0[3])));
            float e[4], loc = 0.0f;
#pragma unroll
            for (int k = 0; k < 4; k++) {
                int s = ln + 32 * k;
                e[k] = (s < Sn) ? expf(v0[k] - mx) : 0.0f;
                loc += e[k];
            }
            float inv = 1.0f / warp_sum(loc);
            size_t pb = ((size_t)t * Bn + (b0 + b)) * Sn;
#pragma unroll
            for (int k = 0; k < 4; k++) {
                int s = ln + 32 * k;
                if (s < Sn) out[pb + s] = e[k] * inv;
            }
            int cand = 1 << 30;
#pragma unroll
            for (int k = 0; k < 4; k++) {
                int s = ln + 32 * k;
                if (s < Sn && v0[k] == mx) cand = min(cand, s);
            }
            cand = warp_min_i(cand);
            if (ln == 0) {
                out[(size_t)Sn * Bn * Sn + (size_t)t * Bn + (b0 + b)] = (float)cand;
                S.mask[b * Sn + cand] = 1;
                S.sidx[b] = cand;
            }
        }
        __syncthreads();

        // gather next decoder input: x[b,:] = emb[idx, b, :]
        for (int i = tid; i < GPB * En; i += NT) {
            int bb = i >> 7, ee = i & 127;
            S.x[i] = emb[((size_t)S.sidx[bb] * Bn + (b0 + bb)) * En + ee];
        }
        __syncthreads();
    }

    // epilogue: final hx, cx
    size_t base = (size_t)Sn * Bn * Sn + (size_t)Sn * Bn;
    for (int i = tid; i < GPB * Hn; i += NT) {
        out[base + b0 * Hn + i] = S.h[i];
        out[base + (size_t)Bn * Hn + b0 * Hn + i] = S.c[i];
    }
}

// ---------------- host launch ------------------------------------------------
extern "C" void kernel_launch(void* const* d_in, const int* in_sizes, int n_in,
                              void* d_out, int out_size) {
    const float* dec = (const float*)d_in[0];
    const float* emb = (const float*)d_in[1];
    const float* h0  = (const float*)d_in[2];
    const float* c0  = (const float*)d_in[3];
    const float* ctx = (const float*)d_in[4];
    const float* Wi  = (const float*)d_in[5];
    const float* bi  = (const float*)d_in[6];
    const float* Wh  = (const float*)d_in[7];
    const float* bh  = (const float*)d_in[8];
    const float* gWq = (const float*)d_in[9];
    const float* gbq = (const float*)d_in[10];
    const float* gWr = (const float*)d_in[11];
    const float* gbr = (const float*)d_in[12];
    const float* gv  = (const float*)d_in[13];
    const float* pWq = (const float*)d_in[14];
    const float* pbq = (const float*)d_in[15];
    const float* pWr = (const float*)d_in[16];
    const float* pbr = (const float*)d_in[17];
    const float* pv  = (const float*)d_in[18];
    float* out = (float*)d_out;

    const int SM_PRE  = (128 * 129 + 128 * 128) * 4;  // 131584
    const int SM_LOOP = (int)sizeof(Smem);
    cudaFuncSetAttribute(k_pre,  cudaFuncAttributeMaxDynamicSharedMemorySize, SM_PRE);
    cudaFuncSetAttribute(k_loop, cudaFuncAttributeMaxDynamicSharedMemorySize, SM_LOOP);

    k_tw<<<256, 256>>>(Wi, Wh, gWq, pWq);
    k_pre<<<dim3(Bn / 128, Sn, 2), 256, SM_PRE>>>(ctx, gWr, gbr, pWr, pbr);
    k_loop<<<NBLK, NT, SM_LOOP>>>(dec, emb, h0, c0, bi, bh,
                                  gbq, gv, pbq, pv, out);
}

// round 13
// speedup vs baseline: 2.6986x; 1.4295x over previous
#include <cuda_runtime.h>
#include <math.h>

#define Bn 1024
#define Sn 100
#define En 128
#define Hn 128
#define GPB 8                 // batches per block
#define NBLK (Bn / GPB)       // 128 persistent blocks
#define NT 512                // threads per block
#define LP 104                // list pitch (Sn padded to multiple of 8)

// ---------------- scratch (device globals; no allocations allowed) ----------
__device__ float d_eg[(size_t)Bn * Sn * Hn];   // raw e_g  [b][s][h]
__device__ float d_tg[(size_t)Bn * Sn * Hn];   // tanh(e_g)
__device__ float d_tp[(size_t)Bn * Sn * Hn];   // tanh(e_p)
__device__ float d_WiT[128 * 128 * 4];         // [k][unit][gate]
__device__ float d_WhT[128 * 128 * 4];         // [k][unit][gate]
__device__ float d_gWqT[128 * 128];            // [k][o]
__device__ float d_pWqT[128 * 128];            // [k][o]

#define NEGINF __int_as_float(0xff800000)

__device__ __forceinline__ float sigf(float x) { return 1.0f / (1.0f + expf(-x)); }

__device__ __forceinline__ float warp_sum(float v) {
#pragma unroll
    for (int o = 16; o > 0; o >>= 1) v += __shfl_xor_sync(0xffffffffu, v, o);
    return v;
}
__device__ __forceinline__ float warp_max(float v) {
#pragma unroll
    for (int o = 16; o > 0; o >>= 1) v = fmaxf(v, __shfl_xor_sync(0xffffffffu, v, o));
    return v;
}
__device__ __forceinline__ int warp_min_i(int v) {
#pragma unroll
    for (int o = 16; o > 0; o >>= 1) v = min(v, __shfl_xor_sync(0xffffffffu, v, o));
    return v;
}

// 8-term attention dot with tree reduction (independent divides, short chain)
__device__ __forceinline__ float dot8(float4 qa, float4 qb, float4 va, float4 vb,
                                      float4 ta, float4 tb) {
    float d0 = va.x * __fdividef(qa.x + ta.x, fmaf(qa.x, ta.x, 1.0f));
    float d1 = va.y * __fdividef(qa.y + ta.y, fmaf(qa.y, ta.y, 1.0f));
    float d2 = va.z * __fdividef(qa.z + ta.z, fmaf(qa.z, ta.z, 1.0f));
    float d3 = va.w * __fdividef(qa.w + ta.w, fmaf(qa.w, ta.w, 1.0f));
    float d4 = vb.x * __fdividef(qb.x + tb.x, fmaf(qb.x, tb.x, 1.0f));
    float d5 = vb.y * __fdividef(qb.y + tb.y, fmaf(qb.y, tb.y, 1.0f));
    float d6 = vb.z * __fdividef(qb.z + tb.z, fmaf(qb.z, tb.z, 1.0f));
    float d7 = vb.w * __fdividef(qb.w + tb.w, fmaf(qb.w, tb.w, 1.0f));
    return ((d0 + d1) + (d2 + d3)) + ((d4 + d5) + (d6 + d7));
}

// ---------------- weight transposes (one-time) -------------------------------
__global__ void k_tw(const float* __restrict__ Wi, const float* __restrict__ Wh,
                     const float* __restrict__ gWq, const float* __restrict__ pWq) {
    int i = blockIdx.x * 256 + threadIdx.x;
    if (i < 65536) {
        int r = i >> 7;          // source row 0..511
        int k = i & 127;
        int g = r >> 7, ul = r & 127;
        d_WiT[(k * 128 + ul) * 4 + g] = Wi[i];
        d_WhT[(k * 128 + ul) * 4 + g] = Wh[i];
    }
    if (i < 16384) {
        int o = i >> 7, k = i & 127;
        d_gWqT[k * 128 + o] = gWq[i];
        d_pWqT[k * 128 + o] = pWq[i];
    }
}

// ---------------- precompute e_g, tanh(e_g), tanh(e_p) ----------------------
__global__ void k_pre(const float* __restrict__ ctx,
                      const float* __restrict__ Wg, const float* __restrict__ bg,
                      const float* __restrict__ Wp, const float* __restrict__ bp) {
    extern __shared__ float sm[];
    float* Wsm = sm;             // [k][o] pitch 129
    float* Csm = sm + 128 * 129; // [k][b] pitch 128
    int b0 = blockIdx.x * 128;
    int s  = blockIdx.y;
    int z  = blockIdx.z;
    const float* W    = z ? Wp : Wg;
    const float* bias = z ? bp : bg;
    int tid = threadIdx.x;

    for (int idx = tid; idx < 128 * 128; idx += 256) {
        int o = idx >> 7, k = idx & 127;
        Wsm[k * 129 + o] = W[idx];
    }
    const float* cbase = ctx + (size_t)s * Hn * Bn + b0;
    for (int idx = tid; idx < 128 * 128; idx += 256) {
        int h = idx >> 7, bb = idx & 127;
        Csm[h * 128 + bb] = cbase[(size_t)h * Bn + bb];
    }
    __syncthreads();

    int tx = tid & 31, ty = tid >> 5;
    float acc[4][16];
#pragma unroll
    for (int i = 0; i < 4; i++)
#pragma unroll
        for (int j = 0; j < 16; j++) acc[i][j] = 0.0f;

    for (int k = 0; k < 128; k++) {
        float wv[4];
#pragma unroll
        for (int i = 0; i < 4; i++) wv[i] = Wsm[k * 129 + tx + 32 * i];
#pragma unroll
        for (int j = 0; j < 16; j++) {
            float cv = Csm[k * 128 + ty * 16 + j];
#pragma unroll
            for (int i = 0; i < 4; i++) acc[i][j] = fmaf(wv[i], cv, acc[i][j]);
        }
    }

#pragma unroll
    for (int j = 0; j < 16; j++) {
        int b = b0 + ty * 16 + j;
#pragma unroll
        for (int i = 0; i < 4; i++) {
            int o = tx + 32 * i;
            float val = acc[i][j] + bias[o];
            size_t off = ((size_t)b * Sn + s) * Hn + o;
            float tv = tanhf(val);
            if (z == 0) { d_eg[off] = val; d_tg[off] = tv; }
            else        { d_tp[off] = tv; }
        }
    }
}

// ---------------- persistent decoder loop ------------------------------------
struct Smem {
    float qWg[128 * 128];          // gWqT resident
    float qWp[128 * 128];          // pWqT resident
    float h[GPB * Hn];
    float c[GPB * Hn];
    float x[GPB * En];
    float tq[GPB * Hn];
    float glA[GPB * Hn];
    float glB[GPB * Hn];
    float u[GPB * Sn];
    float w[GPB * Sn];
    float scr[3 * 4 * GPB * Hn];   // split-k groups 1..3: [gp][gate][b][ul]
    float bias[4 * Hn];
    float gv[Hn];
    float pv[Hn];
    int   list[GPB * LP];
    int   sidx[GPB];
    unsigned char mask[GPB * Sn];
};

__global__ void __launch_bounds__(NT, 1)
k_loop(const float* __restrict__ dec, const float* __restrict__ emb,
       const float* __restrict__ h0,  const float* __restrict__ c0,
       const float* __restrict__ bi,  const float* __restrict__ bh,
       const float* __restrict__ gbq, const float* __restrict__ gv,
       const float* __restrict__ pbq, const float* __restrict__ pv,
       float* __restrict__ out) {
    extern __shared__ unsigned char sm_raw[];
    Smem& S = *reinterpret_cast<Smem*>(sm_raw);

    const int tid = threadIdx.x;
    const int b0  = blockIdx.x * GPB;

    // prologue
    for (int i = tid; i < GPB * Hn; i += NT) {
        S.h[i] = h0[b0 * Hn + i];
        S.c[i] = c0[b0 * Hn + i];
        S.x[i] = dec[b0 * En + i];
    }
    for (int i = tid; i < 4 * Hn; i += NT) S.bias[i] = bi[i] + bh[i];
    for (int i = tid; i < Hn; i += NT) { S.gv[i] = gv[i]; S.pv[i] = pv[i]; }
    for (int i = tid; i < GPB * Sn; i += NT) S.mask[i] = 0;
    for (int i = tid; i < 128 * 128 / 4; i += NT) {
        ((float4*)S.qWg)[i] = ((const float4*)d_gWqT)[i];
        ((float4*)S.qWp)[i] = ((const float4*)d_pWqT)[i];
    }
    __syncthreads();

    const int ul   = tid & 127;      // output lane for GEMMs
    const int kg   = tid >> 7;       // group 0..3
    const int wid  = tid >> 5;       // warp 0..15
    const int ln   = tid & 31;
    const int ab   = wid >> 1;       // attention batch 0..7
    const int wh   = wid & 1;        // which warp of the batch pair
    const int half = ln >> 4;        // half within warp
    const int q16  = ln & 15;

    for (int t = 0; t < Sn; t++) {
        const int m    = Sn - t;           // unmasked count (uniform across b)
        const int mpad = (m + 7) & ~7;
        const int mh   = mpad >> 1;        // per-warp padded share (mult of 4)

        // ===== Stage 0: compact + padded list of unmasked s (warps 0-7) =====
        if (wid < 8) {
            int b = wid;
            int base = 0;
#pragma unroll
            for (int cch = 0; cch < 4; cch++) {
                int s = cch * 32 + ln;
                bool ok = (s < Sn) && (S.mask[b * Sn + s] == 0);
                unsigned bal = __ballot_sync(0xffffffffu, ok);
                if (ok) S.list[b * LP + base + __popc(bal & ((1u << ln) - 1u))] = s;
                base += __popc(bal);
            }
            if (ln == 0) {
                int last = S.list[b * LP + base - 1];
                for (int j = base; j < mpad; j++) S.list[b * LP + j] = last;
            }
        }

        // ===== Stage 1: LSTM gates GEMM, 4-way split-k =====
        {
            const float* WT = (kg < 2) ? d_WiT : d_WhT;
            const float* A  = (kg < 2) ? S.x : S.h;
            const int ko = (kg & 1) * 64;
            float acc[4][GPB];
#pragma unroll
            for (int g = 0; g < 4; g++)
#pragma unroll
                for (int b = 0; b < GPB; b++) acc[g][b] = 0.0f;

#pragma unroll 4
            for (int k = ko; k < ko + 64; k += 4) {
                float4 w0 = *(const float4*)(WT + ((k + 0) * 128 + ul) * 4);
                float4 w1 = *(const float4*)(WT + ((k + 1) * 128 + ul) * 4);
                float4 w2 = *(const float4*)(WT + ((k + 2) * 128 + ul) * 4);
                float4 w3 = *(const float4*)(WT + ((k + 3) * 128 + ul) * 4);
#pragma unroll
                for (int b = 0; b < GPB; b++) {
                    float4 av = *(const float4*)(A + b * 128 + k);
                    acc[0][b] = fmaf(w0.x, av.x, acc[0][b]);
                    acc[0][b] = fmaf(w1.x, av.y, acc[0][b]);
                    acc[0][b] = fmaf(w2.x, av.z, acc[0][b]);
                    acc[0][b] = fmaf(w3.x, av.w, acc[0][b]);
                    acc[1][b] = fmaf(w0.y, av.x, acc[1][b]);
                    acc[1][b] = fmaf(w1.y, av.y, acc[1][b]);
                    acc[1][b] = fmaf(w2.y, av.z, acc[1][b]);
                    acc[1][b] = fmaf(w3.y, av.w, acc[1][b]);
                    acc[2][b] = fmaf(w0.z, av.x, acc[2][b]);
                    acc[2][b] = fmaf(w1.z, av.y, acc[2][b]);
                    acc[2][b] = fmaf(w2.z, av.z, acc[2][b]);
                    acc[2][b] = fmaf(w3.z, av.w, acc[2][b]);
                    acc[3][b] = fmaf(w0.w, av.x, acc[3][b]);
                    acc[3][b] = fmaf(w1.w, av.y, acc[3][b]);
                    acc[3][b] = fmaf(w2.w, av.z, acc[3][b]);
                    acc[3][b] = fmaf(w3.w, av.w, acc[3][b]);
                }
            }
            if (kg != 0) {
#pragma unroll
                for (int g = 0; g < 4; g++)
#pragma unroll
                    for (int b = 0; b < GPB; b++)
                        S.scr[(((kg - 1) * 4 + g) * GPB + b) * 128 + ul] = acc[g][b];
            }
            __syncthreads();

            // combine + cell update by group-0 threads (own accs in registers)
            if (kg == 0) {
                const int u = ul;
#pragma unroll
                for (int b = 0; b < GPB; b++) {
                    float gs[4];
#pragma unroll
                    for (int g = 0; g < 4; g++) {
                        float v = acc[g][b] + S.bias[g * 128 + u];
                        v += S.scr[((0 * 4 + g) * GPB + b) * 128 + u];
                        v += S.scr[((1 * 4 + g) * GPB + b) * 128 + u];
                        v += S.scr[((2 * 4 + g) * GPB + b) * 128 + u];
                        gs[g] = v;
                    }
                    float c  = S.c[b * 128 + u];
                    float cy = sigf(gs[1]) * c + sigf(gs[0]) * tanhf(gs[2]);
                    float hy = sigf(gs[3]) * tanhf(cy);
                    S.c[b * 128 + u] = cy;
                    S.h[b * 128 + u] = hy;
                }
            }
            __syncthreads();
        }

        // ===== Stage 2: tq = tanh(h @ gWq^T + gbq) (smem weights) =====
        {
            int bb0 = kg * 2;
            float a0 = 0.0f, a1 = 0.0f;
            const float* h0p = S.h + bb0 * 128;
            const float* h1p = S.h + (bb0 + 1) * 128;
#pragma unroll 8
            for (int k = 0; k < 128; k++) {
                float wv = S.qWg[k * 128 + ul];
                a0 = fmaf(wv, h0p[k], a0);
                a1 = fmaf(wv, h1p[k], a1);
            }
            float bq = gbq[ul];
            S.tq[bb0 * 128 + ul]       = tanhf(a0 + bq);
            S.tq[(bb0 + 1) * 128 + ul] = tanhf(a1 + bq);
            __syncthreads();
        }

        // ===== Stage 3: glimpse attention (branch-free, 2x unrolled) =====
        {
            const int b = ab;
            const int jbeg = wh * mh + half;
            float4 tqa = *(const float4*)(S.tq + b * 128 + q16 * 8);
            float4 tqb = *(const float4*)(S.tq + b * 128 + q16 * 8 + 4);
            float4 vva = *(const float4*)(S.gv + q16 * 8);
            float4 vvb = *(const float4*)(S.gv + q16 * 8 + 4);
            const float* tgb = d_tg + (size_t)(b0 + b) * Sn * Hn + q16 * 8;
            for (int i = 0; i < (mh >> 2); i++) {
                int j = jbeg + 4 * i;
                int s1 = S.list[b * LP + j];
                int s2 = S.list[b * LP + j + 2];
                const float* r1 = tgb + (size_t)s1 * Hn;
                const float* r2 = tgb + (size_t)s2 * Hn;
                float4 t1a = *(const float4*)(r1);
                float4 t1b = *(const float4*)(r1 + 4);
                float4 t2a = *(const float4*)(r2);
                float4 t2b = *(const float4*)(r2 + 4);
                float a1 = dot8(tqa, tqb, vva, vvb, t1a, t1b);
                float a2 = dot8(tqa, tqb, vva, vvb, t2a, t2b);
#pragma unroll
                for (int o = 8; o > 0; o >>= 1) {
                    a1 += __shfl_xor_sync(0xffffffffu, a1, o);
                    a2 += __shfl_xor_sync(0xffffffffu, a2, o);
                }
                if (q16 == 0) {
                    S.u[b * Sn + s1] = a1;
                    S.u[b * Sn + s2] = a2;
                }
            }
            __syncthreads();
        }

        // ===== Stage 3b: glimpse softmax (warps 0-7) =====
        if (wid < 8) {
            int b = wid;
            float v0[4];
#pragma unroll
            for (int k = 0; k < 4; k++) {
                int s = ln + 32 * k;
                v0[k] = (s < Sn && S.mask[b * Sn + s] == 0) ? S.u[b * Sn + s] : NEGINF;
            }
            float mx = warp_max(fmaxf(fmaxf(v0[0], v0[1]), fmaxf(v0[2], v0[3])));
            float e[4], loc = 0.0f;
#pragma unroll
            for (int k = 0; k < 4; k++) {
                int s = ln + 32 * k;
                e[k] = (s < Sn) ? expf(v0[k] - mx) : 0.0f;
                loc += e[k];
            }
            float inv = 1.0f / warp_sum(loc);
#pragma unroll
            for (int k = 0; k < 4; k++) {
                int s = ln + 32 * k;
                if (s < Sn) S.w[b * Sn + s] = e[k] * inv;
            }
        }
        __syncthreads();

        // ===== Stage 4a: gl = sum_s w*e_g over exact list (2 warps/batch) ====
        {
            const int b = ab;
            const int mh2 = (m + 1) >> 1;
            const int jbeg = wh * mh2;
            const int jend = min(m, jbeg + mh2);
            const float* egb = d_eg + (size_t)(b0 + b) * Sn * Hn + 4 * ln;
            float4 acc = make_float4(0.f, 0.f, 0.f, 0.f);
#pragma unroll 2
            for (int j = jbeg; j < jend; j++) {
                int s = S.list[b * LP + j];
                float ws = S.w[b * Sn + s];
                float4 ev = *(const float4*)(egb + (size_t)s * Hn);
                acc.x = fmaf(ws, ev.x, acc.x);
                acc.y = fmaf(ws, ev.y, acc.y);
                acc.z = fmaf(ws, ev.z, acc.z);
                acc.w = fmaf(ws, ev.w, acc.w);
            }
            float* dst = (wh ? S.glB : S.glA) + b * 128 + 4 * ln;
            *(float4*)dst = acc;
            __syncthreads();
        }

        // ===== Stage 4b: tq = tanh((glA+glB) @ pWq^T + pbq) (smem weights) ===
        {
            int bb0 = kg * 2;
            float a0 = 0.0f, a1 = 0.0f;
            const float* gA0 = S.glA + bb0 * 128;
            const float* gB0 = S.glB + bb0 * 128;
            const float* gA1 = S.glA + (bb0 + 1) * 128;
            const float* gB1 = S.glB + (bb0 + 1) * 128;
#pragma unroll 8
            for (int k = 0; k < 128; k++) {
                float wv = S.qWp[k * 128 + ul];
                a0 = fmaf(wv, gA0[k] + gB0[k], a0);
                a1 = fmaf(wv, gA1[k] + gB1[k], a1);
            }
            float bq = pbq[ul];
            S.tq[bb0 * 128 + ul]       = tanhf(a0 + bq);
            S.tq[(bb0 + 1) * 128 + ul] = tanhf(a1 + bq);
            __syncthreads();
        }

        // ===== Stage 5: pointer attention (branch-free, 2x unrolled) =====
        {
            const int b = ab;
            const int jbeg = wh * mh + half;
            float4 tqa = *(const float4*)(S.tq + b * 128 + q16 * 8);
            float4 tqb = *(const float4*)(S.tq + b * 128 + q16 * 8 + 4);
            float4 vva = *(const float4*)(S.pv + q16 * 8);
            float4 vvb = *(const float4*)(S.pv + q16 * 8 + 4);
            const float* tpb = d_tp + (size_t)(b0 + b) * Sn * Hn + q16 * 8;
            for (int i = 0; i < (mh >> 2); i++) {
                int j = jbeg + 4 * i;
                int s1 = S.list[b * LP + j];
                int s2 = S.list[b * LP + j + 2];
                const float* r1 = tpb + (size_t)s1 * Hn;
                const float* r2 = tpb + (size_t)s2 * Hn;
                float4 t1a = *(const float4*)(r1);
                float4 t1b = *(const float4*)(r1 + 4);
                float4 t2a = *(const float4*)(r2);
                float4 t2b = *(const float4*)(r2 + 4);
                float a1 = dot8(tqa, tqb, vva, vvb, t1a, t1b);
                float a2 = dot8(tqa, tqb, vva, vvb, t2a, t2b);
#pragma unroll
                for (int o = 8; o > 0; o >>= 1) {
                    a1 += __shfl_xor_sync(0xffffffffu, a1, o);
                    a2 += __shfl_xor_sync(0xffffffffu, a2, o);
                }
                if (q16 == 0) {
                    S.u[b * Sn + s1] = 10.0f * tanhf(a1);
                    S.u[b * Sn + s2] = 10.0f * tanhf(a2);
                }
            }
            __syncthreads();
        }

        // ===== Stage 5b: pointer softmax + probs + argmax (warps 0-7) =====
        if (wid < 8) {
            int b = wid;
            float v0[4];
#pragma unroll
            for (int k = 0; k < 4; k++) {
                int s = ln + 32 * k;
                v0[k] = (s < Sn && S.mask[b * Sn + s] == 0) ? S.u[b * Sn + s] : NEGINF;
            }
            float mx = warp_max(fmaxf(fmaxf(v0[0], v0[1]), fmaxf(v0[2], v0[3])));
            float e[4], loc = 0.0f;
#pragma unroll
            for (int k = 0; k < 4; k++) {
                int s = ln + 32 * k;
                e[k] = (s < Sn) ? expf(v0[k] - mx) : 0.0f;
                loc += e[k];
            }
            float inv = 1.0f / warp_sum(loc);
            size_t pb = ((size_t)t * Bn + (b0 + b)) * Sn;
#pragma unroll
            for (int k = 0; k < 4; k++) {
                int s = ln + 32 * k;
                if (s < Sn) out[pb + s] = e[k] * inv;
            }
            int cand = 1 << 30;
#pragma unroll
            for (int k = 0; k < 4; k++) {
                int s = ln + 32 * k;
                if (s < Sn && v0[k] == mx) cand = min(cand, s);
            }
            cand = warp_min_i(cand);
            if (ln == 0) {
                out[(size_t)Sn * Bn * Sn + (size_t)t * Bn + (b0 + b)] = (float)cand;
                S.mask[b * Sn + cand] = 1;
                S.sidx[b] = cand;
            }
        }
        __syncthreads();

        // gather next decoder input: x[b,:] = emb[idx, b, :]
        for (int i = tid; i < GPB * En; i += NT) {
            int bb = i >> 7, ee = i & 127;
            S.x[i] = emb[((size_t)S.sidx[bb] * Bn + (b0 + bb)) * En + ee];
        }
        __syncthreads();
    }

    // epilogue: final hx, cx
    size_t base = (size_t)Sn * Bn * Sn + (size_t)Sn * Bn;
    for (int i = tid; i < GPB * Hn; i += NT) {
        out[base + b0 * Hn + i] = S.h[i];
        out[base + (size_t)Bn * Hn + b0 * Hn + i] = S.c[i];
    }
}

// ---------------- host launch ------------------------------------------------
extern "C" void kernel_launch(void* const* d_in, const int* in_sizes, int n_in,
                              void* d_out, int out_size) {
    const float* dec = (const float*)d_in[0];
    const float* emb = (const float*)d_in[1];
    const float* h0  = (const float*)d_in[2];
    const float* c0  = (const float*)d_in[3];
    const float* ctx = (const float*)d_in[4];
    const float* Wi  = (const float*)d_in[5];
    const float* bi  = (const float*)d_in[6];
    const float* Wh  = (const float*)d_in[7];
    const float* bh  = (const float*)d_in[8];
    const float* gWq = (const float*)d_in[9];
    const float* gbq = (const float*)d_in[10];
    const float* gWr = (const float*)d_in[11];
    const float* gbr = (const float*)d_in[12];
    const float* gv  = (const float*)d_in[13];
    const float* pWq = (const float*)d_in[14];
    const float* pbq = (const float*)d_in[15];
    const float* pWr = (const float*)d_in[16];
    const float* pbr = (const float*)d_in[17];
    const float* pv  = (const float*)d_in[18];
    float* out = (float*)d_out;

    const int SM_PRE  = (128 * 129 + 128 * 128) * 4;  // 131584
    const int SM_LOOP = (int)sizeof(Smem);
    cudaFuncSetAttribute(k_pre,  cudaFuncAttributeMaxDynamicSharedMemorySize, SM_PRE);
    cudaFuncSetAttribute(k_loop, cudaFuncAttributeMaxDynamicSharedMemorySize, SM_LOOP);

    k_tw<<<256, 256>>>(Wi, Wh, gWq, pWq);
    k_pre<<<dim3(Bn / 128, Sn, 2), 256, SM_PRE>>>(ctx, gWr, gbr, pWr, pbr);
    k_loop<<<NBLK, NT, SM_LOOP>>>(dec, emb, h0, c0, bi, bh,
                                  gbq, gv, pbq, pv, out);
}

// round 14
// speedup vs baseline: 3.0573x; 1.1330x over previous
#include <cuda_runtime.h>
#include <math.h>

#define Bn 1024
#define Sn 100
#define En 128
#define Hn 128
#define GPB 8                 // batches per block
#define NBLK (Bn / GPB)       // 128 persistent blocks
#define NT 1024               // threads per block
#define LP 112                // list pitch (Sn padded to multiple of 16)

// ---------------- scratch (device globals; no allocations allowed) ----------
__device__ float d_eg[(size_t)Bn * Sn * Hn];   // raw e_g  [b][s][h]
__device__ float d_tg[(size_t)Bn * Sn * Hn];   // tanh(e_g)
__device__ float d_tp[(size_t)Bn * Sn * Hn];   // tanh(e_p)
__device__ float d_WiT[128 * 128 * 4];         // [k][unit][gate]
__device__ float d_WhT[128 * 128 * 4];         // [k][unit][gate]
__device__ float d_gWqT[128 * 128];            // [k][o]
__device__ float d_pWqT[128 * 128];            // [k][o]

#define NEGINF __int_as_float(0xff800000)

__device__ __forceinline__ float sigf(float x) { return 1.0f / (1.0f + expf(-x)); }

__device__ __forceinline__ float warp_sum(float v) {
#pragma unroll
    for (int o = 16; o > 0; o >>= 1) v += __shfl_xor_sync(0xffffffffu, v, o);
    return v;
}
__device__ __forceinline__ float warp_max(float v) {
#pragma unroll
    for (int o = 16; o > 0; o >>= 1) v = fmaxf(v, __shfl_xor_sync(0xffffffffu, v, o));
    return v;
}
__device__ __forceinline__ int warp_min_i(int v) {
#pragma unroll
    for (int o = 16; o > 0; o >>= 1) v = min(v, __shfl_xor_sync(0xffffffffu, v, o));
    return v;
}

// 8-term attention dot with tree reduction (independent divides, short chain)
__device__ __forceinline__ float dot8(float4 qa, float4 qb, float4 va, float4 vb,
                                      float4 ta, float4 tb) {
    float d0 = va.x * __fdividef(qa.x + ta.x, fmaf(qa.x, ta.x, 1.0f));
    float d1 = va.y * __fdividef(qa.y + ta.y, fmaf(qa.y, ta.y, 1.0f));
    float d2 = va.z * __fdividef(qa.z + ta.z, fmaf(qa.z, ta.z, 1.0f));
    float d3 = va.w * __fdividef(qa.w + ta.w, fmaf(qa.w, ta.w, 1.0f));
    float d4 = vb.x * __fdividef(qb.x + tb.x, fmaf(qb.x, tb.x, 1.0f));
    float d5 = vb.y * __fdividef(qb.y + tb.y, fmaf(qb.y, tb.y, 1.0f));
    float d6 = vb.z * __fdividef(qb.z + tb.z, fmaf(qb.z, tb.z, 1.0f));
    float d7 = vb.w * __fdividef(qb.w + tb.w, fmaf(qb.w, tb.w, 1.0f));
    return ((d0 + d1) + (d2 + d3)) + ((d4 + d5) + (d6 + d7));
}

// ---------------- weight transposes (one-time) -------------------------------
__global__ void k_tw(const float* __restrict__ Wi, const float* __restrict__ Wh,
                     const float* __restrict__ gWq, const float* __restrict__ pWq) {
    int i = blockIdx.x * 256 + threadIdx.x;
    if (i < 65536) {
        int r = i >> 7;          // source row 0..511
        int k = i & 127;
        int g = r >> 7, ul = r & 127;
        d_WiT[(k * 128 + ul) * 4 + g] = Wi[i];
        d_WhT[(k * 128 + ul) * 4 + g] = Wh[i];
    }
    if (i < 16384) {
        int o = i >> 7, k = i & 127;
        d_gWqT[k * 128 + o] = gWq[i];
        d_pWqT[k * 128 + o] = pWq[i];
    }
}

// ---------------- precompute e_g, tanh(e_g), tanh(e_p) ----------------------
__global__ void k_pre(const float* __restrict__ ctx,
                      const float* __restrict__ Wg, const float* __restrict__ bg,
                      const float* __restrict__ Wp, const float* __restrict__ bp) {
    extern __shared__ float sm[];
    float* Wsm = sm;             // [k][o] pitch 129
    float* Csm = sm + 128 * 129; // [k][b] pitch 128
    int b0 = blockIdx.x * 128;
    int s  = blockIdx.y;
    int z  = blockIdx.z;
    const float* W    = z ? Wp : Wg;
    const float* bias = z ? bp : bg;
    int tid = threadIdx.x;

    for (int idx = tid; idx < 128 * 128; idx += 256) {
        int o = idx >> 7, k = idx & 127;
        Wsm[k * 129 + o] = W[idx];
    }
    const float* cbase = ctx + (size_t)s * Hn * Bn + b0;
    for (int idx = tid; idx < 128 * 128; idx += 256) {
        int h = idx >> 7, bb = idx & 127;
        Csm[h * 128 + bb] = cbase[(size_t)h * Bn + bb];
    }
    __syncthreads();

    int tx = tid & 31, ty = tid >> 5;
    float acc[4][16];
#pragma unroll
    for (int i = 0; i < 4; i++)
#pragma unroll
        for (int j = 0; j < 16; j++) acc[i][j] = 0.0f;

    for (int k = 0; k < 128; k++) {
        float wv[4];
#pragma unroll
        for (int i = 0; i < 4; i++) wv[i] = Wsm[k * 129 + tx + 32 * i];
#pragma unroll
        for (int j = 0; j < 16; j++) {
            float cv = Csm[k * 128 + ty * 16 + j];
#pragma unroll
            for (int i = 0; i < 4; i++) acc[i][j] = fmaf(wv[i], cv, acc[i][j]);
        }
    }

#pragma unroll
    for (int j = 0; j < 16; j++) {
        int b = b0 + ty * 16 + j;
#pragma unroll
        for (int i = 0; i < 4; i++) {
            int o = tx + 32 * i;
            float val = acc[i][j] + bias[o];
            size_t off = ((size_t)b * Sn + s) * Hn + o;
            float tv = tanhf(val);
            if (z == 0) { d_eg[off] = val; d_tg[off] = tv; }
            else        { d_tp[off] = tv; }
        }
    }
}

// ---------------- persistent decoder loop ------------------------------------
struct Smem {
    float qWg[128 * 128];          // gWqT resident [k][o]
    float qWp[128 * 128];          // pWqT resident [k][o]
    float h[GPB * Hn];
    float c[GPB * Hn];
    float x[GPB * En];
    float tq[GPB * Hn];
    float glA[GPB * Hn];
    float glB[GPB * Hn];
    float glC[GPB * Hn];
    float glD[GPB * Hn];
    float u[GPB * Sn];
    float w[GPB * Sn];
    float scr[3 * 4 * GPB * Hn];   // gates split-k groups 1..3; reused by q-gemms
    float bias[4 * Hn];
    float bqg[Hn];
    float bqp[Hn];
    float gv[Hn];
    float pv[Hn];
    int   list[GPB * LP];
    int   sidx[GPB];
    unsigned char mask[GPB * Sn];
};

__global__ void __launch_bounds__(NT, 1)
k_loop(const float* __restrict__ dec, const float* __restrict__ emb,
       const float* __restrict__ h0,  const float* __restrict__ c0,
       const float* __restrict__ bi,  const float* __restrict__ bh,
       const float* __restrict__ gbq, const float* __restrict__ gv,
       const float* __restrict__ pbq, const float* __restrict__ pv,
       float* __restrict__ out) {
    extern __shared__ unsigned char sm_raw[];
    Smem& S = *reinterpret_cast<Smem*>(sm_raw);

    const int tid = threadIdx.x;
    const int b0  = blockIdx.x * GPB;

    // prologue
    for (int i = tid; i < GPB * Hn; i += NT) {
        S.h[i] = h0[b0 * Hn + i];
        S.c[i] = c0[b0 * Hn + i];
        S.x[i] = dec[b0 * En + i];
    }
    for (int i = tid; i < 4 * Hn; i += NT) S.bias[i] = bi[i] + bh[i];
    if (tid < Hn) {
        S.gv[tid]  = gv[tid];
        S.pv[tid]  = pv[tid];
        S.bqg[tid] = gbq[tid];
        S.bqp[tid] = pbq[tid];
    }
    for (int i = tid; i < GPB * Sn; i += NT) S.mask[i] = 0;
    for (int i = tid; i < 128 * 128 / 4; i += NT) {
        ((float4*)S.qWg)[i] = ((const float4*)d_gWqT)[i];
        ((float4*)S.qWp)[i] = ((const float4*)d_pWqT)[i];
    }
    __syncthreads();

    const int ul   = tid & 127;      // output lane for GEMMs
    const int grp  = tid >> 7;       // group 0..7
    const int wid  = tid >> 5;       // warp 0..31
    const int ln   = tid & 31;
    const int ab   = wid >> 2;       // attention batch 0..7
    const int w4   = wid & 3;        // which of 4 warps of the batch
    const int half = ln >> 4;        // half within warp
    const int q16  = ln & 15;

    // gates mapping: kg = k/W selector (0..3), bhh = batch-half offset
    const int kg  = grp >> 1;
    const int bhh = (grp & 1) * 4;
    // q-gemm mapping: bg2 = batch pair, kh = k half
    const int bg2 = grp & 3;
    const int kh  = grp >> 2;
    const int bA  = bg2 * 2, bB = bg2 * 2 + 1;

    for (int t = 0; t < Sn; t++) {
        const int m      = Sn - t;             // unmasked count (uniform)
        const int mpad16 = (m + 15) & ~15;

        // ===== Stage 0: compact + padded list of unmasked s (warps 0-7) =====
        if (wid < 8) {
            int b = wid;
            int base = 0;
#pragma unroll
            for (int cch = 0; cch < 4; cch++) {
                int s = cch * 32 + ln;
                bool ok = (s < Sn) && (S.mask[b * Sn + s] == 0);
                unsigned bal = __ballot_sync(0xffffffffu, ok);
                if (ok) S.list[b * LP + base + __popc(bal & ((1u << ln) - 1u))] = s;
                base += __popc(bal);
            }
            if (ln == 0) {
                int last = S.list[b * LP + base - 1];
                for (int j = base; j < mpad16; j++) S.list[b * LP + j] = last;
            }
        }

        // ===== Stage 1: LSTM gates GEMM, 4-way split-k x 2-way split-batch ===
        {
            const float* WT = (kg < 2) ? d_WiT : d_WhT;
            const float* A  = ((kg < 2) ? S.x : S.h) + bhh * 128;
            const int ko = (kg & 1) * 64;
            float acc[4][4];
#pragma unroll
            for (int g = 0; g < 4; g++)
#pragma unroll
                for (int b = 0; b < 4; b++) acc[g][b] = 0.0f;

#pragma unroll 4
            for (int k = ko; k < ko + 64; k += 4) {
                float4 w0 = *(const float4*)(WT + ((k + 0) * 128 + ul) * 4);
                float4 w1 = *(const float4*)(WT + ((k + 1) * 128 + ul) * 4);
                float4 w2 = *(const float4*)(WT + ((k + 2) * 128 + ul) * 4);
                float4 w3 = *(const float4*)(WT + ((k + 3) * 128 + ul) * 4);
#pragma unroll
                for (int b = 0; b < 4; b++) {
                    float4 av = *(const float4*)(A + b * 128 + k);
                    acc[0][b] = fmaf(w0.x, av.x, acc[0][b]);
                    acc[0][b] = fmaf(w1.x, av.y, acc[0][b]);
                    acc[0][b] = fmaf(w2.x, av.z, acc[0][b]);
                    acc[0][b] = fmaf(w3.x, av.w, acc[0][b]);
                    acc[1][b] = fmaf(w0.y, av.x, acc[1][b]);
                    acc[1][b] = fmaf(w1.y, av.y, acc[1][b]);
                    acc[1][b] = fmaf(w2.y, av.z, acc[1][b]);
                    acc[1][b] = fmaf(w3.y, av.w, acc[1][b]);
                    acc[2][b] = fmaf(w0.z, av.x, acc[2][b]);
                    acc[2][b] = fmaf(w1.z, av.y, acc[2][b]);
                    acc[2][b] = fmaf(w2.z, av.z, acc[2][b]);
                    acc[2][b] = fmaf(w3.z, av.w, acc[2][b]);
                    acc[3][b] = fmaf(w0.w, av.x, acc[3][b]);
                    acc[3][b] = fmaf(w1.w, av.y, acc[3][b]);
                    acc[3][b] = fmaf(w2.w, av.z, acc[3][b]);
                    acc[3][b] = fmaf(w3.w, av.w, acc[3][b]);
                }
            }
            if (kg != 0) {
#pragma unroll
                for (int g = 0; g < 4; g++)
#pragma unroll
                    for (int b = 0; b < 4; b++)
                        S.scr[(((kg - 1) * 4 + g) * GPB + bhh + b) * 128 + ul] = acc[g][b];
            }
            __syncthreads();

            // combine + cell update by kg==0 threads (accs in registers)
            if (kg == 0) {
#pragma unroll
                for (int b = 0; b < 4; b++) {
                    int gb = bhh + b;
                    float gs[4];
#pragma unroll
                    for (int g = 0; g < 4; g++) {
                        float v = acc[g][b] + S.bias[g * 128 + ul];
                        v += S.scr[((0 * 4 + g) * GPB + gb) * 128 + ul];
                        v += S.scr[((1 * 4 + g) * GPB + gb) * 128 + ul];
                        v += S.scr[((2 * 4 + g) * GPB + gb) * 128 + ul];
                        gs[g] = v;
                    }
                    float c  = S.c[gb * 128 + ul];
                    float cy = sigf(gs[1]) * c + sigf(gs[0]) * tanhf(gs[2]);
                    float hy = sigf(gs[3]) * tanhf(cy);
                    S.c[gb * 128 + ul] = cy;
                    S.h[gb * 128 + ul] = hy;
                }
            }
            __syncthreads();
        }

        // ===== Stage 2: tq = tanh(h @ gWq^T + gbq), 2-way split-k =====
        {
            const int koff = kh * 64;
            float a0 = 0.0f, a1 = 0.0f;
            const float* hA = S.h + bA * 128 + koff;
            const float* hB = S.h + bB * 128 + koff;
            const float* Wp_ = S.qWg + koff * 128 + ul;
#pragma unroll 8
            for (int k = 0; k < 64; k++) {
                float wv = Wp_[k * 128];
                a0 = fmaf(wv, hA[k], a0);
                a1 = fmaf(wv, hB[k], a1);
            }
            if (kh == 1) {
                S.scr[bA * 128 + ul] = a0;
                S.scr[bB * 128 + ul] = a1;
            }
            __syncthreads();
            if (kh == 0) {
                float bq = S.bqg[ul];
                S.tq[bA * 128 + ul] = tanhf(a0 + S.scr[bA * 128 + ul] + bq);
                S.tq[bB * 128 + ul] = tanhf(a1 + S.scr[bB * 128 + ul] + bq);
            }
            __syncthreads();
        }

        // ===== Stage 3: glimpse attention (4 warps/batch, branch-free) =====
        {
            const int b = ab;
            const int nI = mpad16 >> 4;
            float4 tqa = *(const float4*)(S.tq + b * 128 + q16 * 8);
            float4 tqb = *(const float4*)(S.tq + b * 128 + q16 * 8 + 4);
            float4 vva = *(const float4*)(S.gv + q16 * 8);
            float4 vvb = *(const float4*)(S.gv + q16 * 8 + 4);
            const float* tgb = d_tg + (size_t)(b0 + b) * Sn * Hn + q16 * 8;
            for (int i = 0; i < nI; i++) {
                int j0 = 16 * i + 4 * w4;
                int s1 = S.list[b * LP + j0 + half];
                int s2 = S.list[b * LP + j0 + 2 + half];
                const float* r1 = tgb + (size_t)s1 * Hn;
                const float* r2 = tgb + (size_t)s2 * Hn;
                float4 t1a = *(const float4*)(r1);
                float4 t1b = *(const float4*)(r1 + 4);
                float4 t2a = *(const float4*)(r2);
                float4 t2b = *(const float4*)(r2 + 4);
                float a1 = dot8(tqa, tqb, vva, vvb, t1a, t1b);
                float a2 = dot8(tqa, tqb, vva, vvb, t2a, t2b);
#pragma unroll
                for (int o = 8; o > 0; o >>= 1) {
                    a1 += __shfl_xor_sync(0xffffffffu, a1, o);
                    a2 += __shfl_xor_sync(0xffffffffu, a2, o);
                }
                if (q16 == 0) {
                    S.u[b * Sn + s1] = a1;
                    S.u[b * Sn + s2] = a2;
                }
            }
            __syncthreads();
        }

        // ===== Stage 3b: glimpse softmax (warps 0-7) =====
        if (wid < 8) {
            int b = wid;
            float v0[4];
#pragma unroll
            for (int k = 0; k < 4; k++) {
                int s = ln + 32 * k;
                v0[k] = (s < Sn && S.mask[b * Sn + s] == 0) ? S.u[b * Sn + s] : NEGINF;
            }
            float mx = warp_max(fmaxf(fmaxf(v0[0], v0[1]), fmaxf(v0[2], v0[3])));
            float e[4], loc = 0.0f;
#pragma unroll
            for (int k = 0; k < 4; k++) {
                int s = ln + 32 * k;
                e[k] = (s < Sn) ? expf(v0[k] - mx) : 0.0f;
                loc += e[k];
            }
            float inv = 1.0f / warp_sum(loc);
#pragma unroll
            for (int k = 0; k < 4; k++) {
                int s = ln + 32 * k;
                if (s < Sn) S.w[b * Sn + s] = e[k] * inv;
            }
        }
        __syncthreads();

        // ===== Stage 4a: gl partials over exact list (4 warps/batch) =====
        {
            const int b = ab;
            const int mq = (m + 3) >> 2;
            const int jbeg = w4 * mq;
            const int jend = min(m, jbeg + mq);
            const float* egb = d_eg + (size_t)(b0 + b) * Sn * Hn + 4 * ln;
            float4 acc = make_float4(0.f, 0.f, 0.f, 0.f);
#pragma unroll 2
            for (int j = jbeg; j < jend; j++) {
                int s = S.list[b * LP + j];
                float ws = S.w[b * Sn + s];
                float4 ev = *(const float4*)(egb + (size_t)s * Hn);
                acc.x = fmaf(ws, ev.x, acc.x);
                acc.y = fmaf(ws, ev.y, acc.y);
                acc.z = fmaf(ws, ev.z, acc.z);
                acc.w = fmaf(ws, ev.w, acc.w);
            }
            float* dst = (w4 == 0 ? S.glA : w4 == 1 ? S.glB : w4 == 2 ? S.glC : S.glD)
                         + b * 128 + 4 * ln;
            *(float4*)dst = acc;
            __syncthreads();
            // sum the 4 partials (1 element per thread)
            float v = S.glA[tid] + S.glB[tid] + S.glC[tid] + S.glD[tid];
            __syncthreads();
            S.glA[tid] = v;
            __syncthreads();
        }

        // ===== Stage 4b: tq = tanh(gl @ pWq^T + pbq), 2-way split-k =====
        {
            const int koff = kh * 64;
            float a0 = 0.0f, a1 = 0.0f;
            const float* gA = S.glA + bA * 128 + koff;
            const float* gB = S.glA + bB * 128 + koff;
            const float* Wp_ = S.qWp + koff * 128 + ul;
#pragma unroll 8
            for (int k = 0; k < 64; k++) {
                float wv = Wp_[k * 128];
                a0 = fmaf(wv, gA[k], a0);
                a1 = fmaf(wv, gB[k], a1);
            }
            if (kh == 1) {
                S.scr[bA * 128 + ul] = a0;
                S.scr[bB * 128 + ul] = a1;
            }
            __syncthreads();
            if (kh == 0) {
                float bq = S.bqp[ul];
                S.tq[bA * 128 + ul] = tanhf(a0 + S.scr[bA * 128 + ul] + bq);
                S.tq[bB * 128 + ul] = tanhf(a1 + S.scr[bB * 128 + ul] + bq);
            }
            __syncthreads();
        }

        // ===== Stage 5: pointer attention (4 warps/batch, branch-free) =====
        {
            const int b = ab;
            const int nI = mpad16 >> 4;
            float4 tqa = *(const float4*)(S.tq + b * 128 + q16 * 8);
            float4 tqb = *(const float4*)(S.tq + b * 128 + q16 * 8 + 4);
            float4 vva = *(const float4*)(S.pv + q16 * 8);
            float4 vvb = *(const float4*)(S.pv + q16 * 8 + 4);
            const float* tpb = d_tp + (size_t)(b0 + b) * Sn * Hn + q16 * 8;
            for (int i = 0; i < nI; i++) {
                int j0 = 16 * i + 4 * w4;
                int s1 = S.list[b * LP + j0 + half];
                int s2 = S.list[b * LP + j0 + 2 + half];
                const float* r1 = tpb + (size_t)s1 * Hn;
                const float* r2 = tpb + (size_t)s2 * Hn;
                float4 t1a = *(const float4*)(r1);
                float4 t1b = *(const float4*)(r1 + 4);
                float4 t2a = *(const float4*)(r2);
                float4 t2b = *(const float4*)(r2 + 4);
                float a1 = dot8(tqa, tqb, vva, vvb, t1a, t1b);
                float a2 = dot8(tqa, tqb, vva, vvb, t2a, t2b);
#pragma unroll
                for (int o = 8; o > 0; o >>= 1) {
                    a1 += __shfl_xor_sync(0xffffffffu, a1, o);
                    a2 += __shfl_xor_sync(0xffffffffu, a2, o);
                }
                if (q16 == 0) {
                    S.u[b * Sn + s1] = 10.0f * tanhf(a1);
                    S.u[b * Sn + s2] = 10.0f * tanhf(a2);
                }
            }
            __syncthreads();
        }

        // ===== Stage 5b: pointer softmax + probs + argmax (warps 0-7) =====
        if (wid < 8) {
            int b = wid;
            float v0[4];
#pragma unroll
            for (int k = 0; k < 4; k++) {
                int s = ln + 32 * k;
                v0[k] = (s < Sn && S.mask[b * Sn + s] == 0) ? S.u[b * Sn + s] : NEGINF;
            }
            float mx = warp_max(fmaxf(fmaxf(v0[0], v0[1]), fmaxf(v0[2], v0[3])));
            float e[4], loc = 0.0f;
#pragma unroll
            for (int k = 0; k < 4; k++) {
                int s = ln + 32 * k;
                e[k] = (s < Sn) ? expf(v0[k] - mx) : 0.0f;
                loc += e[k];
            }
            float inv = 1.0f / warp_sum(loc);
            size_t pb = ((size_t)t * Bn + (b0 + b)) * Sn;
#pragma unroll
            for (int k = 0; k < 4; k++) {
                int s = ln + 32 * k;
                if (s < Sn) out[pb + s] = e[k] * inv;
            }
            int cand = 1 << 30;
#pragma unroll
            for (int k = 0; k < 4; k++) {
                int s = ln + 32 * k;
                if (s < Sn && v0[k] == mx) cand = min(cand, s);
            }
            cand = warp_min_i(cand);
            if (ln == 0) {
                out[(size_t)Sn * Bn * Sn + (size_t)t * Bn + (b0 + b)] = (float)cand;
                S.mask[b * Sn + cand] = 1;
                S.sidx[b] = cand;
            }
        }
        __syncthreads();

        // gather next decoder input: x[b,:] = emb[idx, b, :] (1 elem/thread)
        {
            int bb = tid >> 7, ee = tid & 127;
            S.x[tid] = emb[((size_t)S.sidx[bb] * Bn + (b0 + bb)) * En + ee];
        }
        __syncthreads();
    }

    // epilogue: final hx, cx
    size_t base = (size_t)Sn * Bn * Sn + (size_t)Sn * Bn;
    for (int i = tid; i < GPB * Hn; i += NT) {
        out[base + b0 * Hn + i] = S.h[i];
        out[base + (size_t)Bn * Hn + b0 * Hn + i] = S.c[i];
    }
}

// ---------------- host launch ------------------------------------------------
extern "C" void kernel_launch(void* const* d_in, const int* in_sizes, int n_in,
                              void* d_out, int out_size) {
    const float* dec = (const float*)d_in[0];
    const float* emb = (const float*)d_in[1];
    const float* h0  = (const float*)d_in[2];
    const float* c0  = (const float*)d_in[3];
    const float* ctx = (const float*)d_in[4];
    const float* Wi  = (const float*)d_in[5];
    const float* bi  = (const float*)d_in[6];
    const float* Wh  = (const float*)d_in[7];
    const float* bh  = (const float*)d_in[8];
    const float* gWq = (const float*)d_in[9];
    const float* gbq = (const float*)d_in[10];
    const float* gWr = (const float*)d_in[11];
    const float* gbr = (const float*)d_in[12];
    const float* gv  = (const float*)d_in[13];
    const float* pWq = (const float*)d_in[14];
    const float* pbq = (const float*)d_in[15];
    const float* pWr = (const float*)d_in[16];
    const float* pbr = (const float*)d_in[17];
    const float* pv  = (const float*)d_in[18];
    float* out = (float*)d_out;

    const int SM_PRE  = (128 * 129 + 128 * 128) * 4;  // 131584
    const int SM_LOOP = (int)sizeof(Smem);
    cudaFuncSetAttribute(k_pre,  cudaFuncAttributeMaxDynamicSharedMemorySize, SM_PRE);
    cudaFuncSetAttribute(k_loop, cudaFuncAttributeMaxDynamicSharedMemorySize, SM_LOOP);

    k_tw<<<256, 256>>>(Wi, Wh, gWq, pWq);
    k_pre<<<dim3(Bn / 128, Sn, 2), 256, SM_PRE>>>(ctx, gWr, gbr, pWr, pbr);
    k_loop<<<NBLK, NT, SM_LOOP>>>(dec, emb, h0, c0, bi, bh,
                                  gbq, gv, pbq, pv, out);
}